// round 7
// baseline (speedup 1.0000x reference)
#include <cuda_runtime.h>
#include <cuda_fp16.h>

#define NHID 32

// fp32 folded coefficients: per j: 9 K coeffs + W2[j][0..1] + pad
__device__ float g_const[NHID * 12];
// B fragments for mma.sync.m16n8k16: [kstep][ntile][reg][lane]
// KK rows: 0-8 = K_hi, 9-17 = K_hi (x F_lo), 18-26 = K_lo (x F_hi), 27-31 = 0.
__device__ unsigned int g_Bfrag[2][4][2][32];

struct cpx { float x, y; };

__device__ __forceinline__ void apply1q(cpx* s, cpx m00, cpx m01, cpx m10, cpx m11, int wire)
{
    int st = 1 << (2 - wire);
    for (int i = 0; i < 8; i++) {
        if (i & st) continue;
        cpx a = s[i], b = s[i + st];
        cpx n0 = { m00.x*a.x - m00.y*a.y + m01.x*b.x - m01.y*b.y,
                   m00.x*a.y + m00.y*a.x + m01.x*b.y + m01.y*b.x };
        cpx n1 = { m10.x*a.x - m10.y*a.y + m11.x*b.x - m11.y*b.y,
                   m10.x*a.y + m10.y*a.x + m11.x*b.y + m11.y*b.x };
        s[i] = n0; s[i + st] = n1;
    }
}

__device__ __forceinline__ void applyCRX(cpx* s, float c, float sn, int ctrl, int tgt)
{
    int cs = 1 << (2 - ctrl), ts = 1 << (2 - tgt);
    for (int i = 0; i < 8; i++) {
        if (!(i & cs) || (i & ts)) continue;
        cpx a = s[i], b = s[i + ts];
        s[i]      = { c*a.x + sn*b.y, c*a.y - sn*b.x };
        s[i + ts] = { c*b.x + sn*a.y, c*b.y - sn*a.x };
    }
}

__global__ void setup_kernel(const float* __restrict__ theta,
                             const float* __restrict__ W1,
                             const float* __restrict__ b1,
                             const float* __restrict__ W2)
{
    __shared__ cpx Vs[4][8];
    int tid = threadIdx.x;

    if (tid < 4) {
        cpx s[8];
        for (int i = 0; i < 8; i++) s[i] = {0.f, 0.f};
        s[tid * 2] = {1.f, 0.f};
        float c, sn;
        sincosf(0.5f * theta[0], &sn, &c);
        apply1q(s, {c,0.f},{0.f,-sn},{0.f,-sn},{c,0.f}, 0);
        sincosf(0.5f * theta[1], &sn, &c);
        apply1q(s, {c,0.f},{-sn,0.f},{sn,0.f},{c,0.f}, 1);
        sincosf(0.5f * theta[2], &sn, &c);
        apply1q(s, {c,-sn},{0.f,0.f},{0.f,0.f},{c,sn}, 2);
        sincosf(0.5f * theta[3], &sn, &c);
        applyCRX(s, c, sn, 0, 1);
        sincosf(0.5f * theta[4], &sn, &c);
        apply1q(s, {c,0.f},{-sn,0.f},{sn,0.f},{c,0.f}, 2);
        sincosf(0.5f * theta[5], &sn, &c);
        apply1q(s, {c,0.f},{0.f,-sn},{0.f,-sn},{c,0.f}, 1);
        sincosf(0.5f * theta[6], &sn, &c);
        applyCRX(s, c, sn, 1, 2);
        sincosf(0.5f * theta[7], &sn, &c);
        apply1q(s, {c,-sn},{0.f,0.f},{0.f,0.f},{c,sn}, 0);
        for (int k = 0; k < 8; k++)
            Vs[tid][k] = (tid >= 2) ? cpx{ s[k].y, -s[k].x } : s[k]; // * (-i)
    }
    __syncwarp();

    int j = tid;
    float M[4][4];
    for (int a = 0; a < 4; a++)
        for (int b = 0; b < 4; b++) {
            float m = 0.f;
            for (int k = 0; k < 8; k++)
                m += W1[k * NHID + j] * (Vs[a][k].x * Vs[b][k].x + Vs[a][k].y * Vs[b][k].y);
            M[a][b] = m;
        }

    const float R[2][2][3] = { { {0.5f, 0.5f, 0.f}, {0.f, 0.f, 0.5f} },
                               { {0.f, 0.f, 0.5f}, {0.5f, -0.5f, 0.f} } };
    float K[3][3] = { {0.f,0.f,0.f},{0.f,0.f,0.f},{0.f,0.f,0.f} };
    for (int a = 0; a < 4; a++)
        for (int b = 0; b < 4; b++) {
            int ia = a >> 1, ja = a & 1, ib = b >> 1, jb = b & 1;
            float Mab = M[a][b];
            for (int m = 0; m < 3; m++)
                for (int n = 0; n < 3; n++)
                    K[m][n] += Mab * R[ia][ib][m] * R[ja][jb][n];
        }
    K[0][0] += b1[j];

    float cf[9];
    for (int t = 0; t < 9; t++) cf[t] = K[t / 3][t % 3];

    for (int t = 0; t < 9; t++) g_const[j * 12 + t] = cf[t];
    g_const[j * 12 + 9]  = W2[j * 2 + 0];
    g_const[j * 12 + 10] = W2[j * 2 + 1];
    g_const[j * 12 + 11] = 0.f;

    float chi[9], clo[9];
    for (int i = 0; i < 9; i++) {
        chi[i] = __half2float(__float2half_rn(cf[i]));
        clo[i] = cf[i] - chi[i];
    }
    int nt = j >> 3, g = j & 7;
    for (int ks = 0; ks < 2; ks++)
        for (int r = 0; r < 2; r++)
            for (int t = 0; t < 4; t++) {
                int r0 = ks * 16 + 2 * t + r * 8;
                #define KKROW(rr) ((rr) < 9 ? chi[(rr)] : (rr) < 18 ? chi[(rr)-9] : (rr) < 27 ? clo[(rr)-18] : 0.f)
                float v0 = KKROW(r0);
                float v1 = KKROW(r0 + 1);
                #undef KKROW
                __half2 h2 = __floats2half2_rn(v0, v1);
                g_Bfrag[ks][nt][r][g * 4 + t] = *reinterpret_cast<unsigned int*>(&h2);
            }
}

__device__ __forceinline__ void mma16816(float c[4],
                                         unsigned a0, unsigned a1, unsigned a2, unsigned a3,
                                         unsigned b0, unsigned b1)
{
    asm volatile(
        "mma.sync.aligned.m16n8k16.row.col.f32.f16.f16.f32 "
        "{%0,%1,%2,%3}, {%4,%5,%6,%7}, {%8,%9}, {%0,%1,%2,%3};"
        : "+f"(c[0]), "+f"(c[1]), "+f"(c[2]), "+f"(c[3])
        : "r"(a0), "r"(a1), "r"(a2), "r"(a3), "r"(b0), "r"(b1));
}

// ---- packed f32x2 helpers (scalar path) ----
typedef unsigned long long u64;
__device__ __forceinline__ u64 pk2(float lo, float hi) {
    u64 r; asm("mov.b64 %0, {%1,%2};" : "=l"(r) : "f"(lo), "f"(hi)); return r;
}
__device__ __forceinline__ void upk2(u64 v, float& lo, float& hi) {
    asm("mov.b64 {%0,%1}, %2;" : "=f"(lo), "=f"(hi) : "l"(v));
}
__device__ __forceinline__ u64 ffma2(u64 a, u64 b, u64 c) {
    u64 d; asm("fma.rn.f32x2 %0, %1, %2, %3;" : "=l"(d) : "l"(a), "l"(b), "l"(c)); return d;
}
__device__ __forceinline__ u64 relu2(u64 v) {
    float lo, hi;
    upk2(v, lo, hi);
    return pk2(fmaxf(lo, 0.f), fmaxf(hi, 0.f));
}

// Hybrid: per 16 blocks, 13 run the tensor-core path (256 samples each) and
// 3 run the fp32 FFMA2 path (1024 samples each). Both warp species co-reside
// on every SM, filling each other's stall cycles.
__global__ void __launch_bounds__(256, 4)
qmlp_hybrid(const float* __restrict__ x,
            const float* __restrict__ W2,
            const float* __restrict__ b2,
            float* __restrict__ out, int B, int M_TOT)
{
    __shared__ __align__(16) __half sA[8][32 * 40];
    __shared__ __align__(16) float  sX[8][96];
    __shared__ float sd[NHID * 24];

    int sg = blockIdx.x >> 4;
    int r  = blockIdx.x & 15;

    if (r < 13) {
        // ================= MMA path =================
        int m_id = sg * 13 + r;
        long long base = (long long)m_id * 256;
        if (base >= M_TOT) return;

        int lane = threadIdx.x & 31;
        int warp = threadIdx.x >> 5;
        base += (long long)warp * 32;
        int g = lane >> 2, t = lane & 3;

        // uniform operands (L1-cached)
        unsigned bf[2][4][2];
        #pragma unroll
        for (int ks = 0; ks < 2; ks++)
            #pragma unroll
            for (int nt = 0; nt < 4; nt++) {
                bf[ks][nt][0] = __ldg(&g_Bfrag[ks][nt][0][lane]);
                bf[ks][nt][1] = __ldg(&g_Bfrag[ks][nt][1][lane]);
            }
        float2 wA[4], wB[4];
        #pragma unroll
        for (int nt = 0; nt < 4; nt++) {
            int j0 = nt * 8 + 2 * t;
            wA[nt] = __ldg(reinterpret_cast<const float2*>(W2 + (size_t)j0 * 2));
            wB[nt] = __ldg(reinterpret_cast<const float2*>(W2 + (size_t)(j0 + 1) * 2));
        }
        float bias0 = __ldg(&b2[0]);
        float bias1 = __ldg(&b2[1]);

        // vectorized x load via smem transpose (stride-3 LDS: conflict-free)
        const float4* xg = reinterpret_cast<const float4*>(x + base * 3);
        if (lane < 24)
            reinterpret_cast<float4*>(sX[warp])[lane] = xg[lane];
        __syncwarp();
        float xa = sX[warp][lane * 3];
        float xb = sX[warp][lane * 3 + 1];   // x[...+2] is a global phase

        float s0n, c0n, s1n, c1n;
        __sincosf(xa, &s0n, &c0n);
        __sincosf(xb, &s1n, &c1n);
        float F[9] = { 1.f, c1n, s1n, c0n, c0n*c1n, c0n*s1n, s0n, s0n*c1n, s0n*s1n };
        float lo[9];
        #pragma unroll
        for (int i = 0; i < 9; i++)
            lo[i] = F[i] - __half2float(__float2half_rn(F[i]));

        // A row (32 halves): cols 0-8 F_hi, 9-17 F_lo, 18-26 F_hi, 27-31 zero.
        // Packs for cols 18-25 duplicate cols 0-7 -> reuse registers.
        unsigned w[16];
        __half2 h2;
        #define PACK(a, b) (h2 = __floats2half2_rn((a), (b)), *reinterpret_cast<unsigned*>(&h2))
        w[0]  = PACK(F[0], F[1]);
        w[1]  = PACK(F[2], F[3]);
        w[2]  = PACK(F[4], F[5]);
        w[3]  = PACK(F[6], F[7]);
        w[4]  = PACK(F[8], lo[0]);
        w[5]  = PACK(lo[1], lo[2]);
        w[6]  = PACK(lo[3], lo[4]);
        w[7]  = PACK(lo[5], lo[6]);
        w[8]  = PACK(lo[7], lo[8]);
        w[9]  = w[0]; w[10] = w[1]; w[11] = w[2]; w[12] = w[3];
        w[13] = PACK(F[8], 0.f);
        w[14] = 0u; w[15] = 0u;
        #undef PACK

        uint4* rp = reinterpret_cast<uint4*>(&sA[warp][lane * 40]);
        rp[0] = make_uint4(w[0],  w[1],  w[2],  w[3]);
        rp[1] = make_uint4(w[4],  w[5],  w[6],  w[7]);
        rp[2] = make_uint4(w[8],  w[9],  w[10], w[11]);
        rp[3] = make_uint4(w[12], w[13], w[14], w[15]);
        __syncwarp();

        const unsigned* sw = reinterpret_cast<const unsigned*>(sA[warp]);  // 20 words/row

        #pragma unroll
        for (int tile = 0; tile < 2; tile++) {
            float acc[4][4];
            #pragma unroll
            for (int nt = 0; nt < 4; nt++)
                #pragma unroll
                for (int c = 0; c < 4; c++) acc[nt][c] = 0.f;

            int r0w = (tile * 16 + g) * 20;
            int r1w = (tile * 16 + g + 8) * 20;
            #pragma unroll
            for (int ks = 0; ks < 2; ks++) {
                unsigned a0 = sw[r0w + ks * 8 + t];
                unsigned a1 = sw[r1w + ks * 8 + t];
                unsigned a2 = sw[r0w + ks * 8 + t + 4];
                unsigned a3 = sw[r1w + ks * 8 + t + 4];
                #pragma unroll
                for (int nt = 0; nt < 4; nt++)
                    mma16816(acc[nt], a0, a1, a2, a3, bf[ks][nt][0], bf[ks][nt][1]);
            }

            float p0 = 0.f, p1 = 0.f, q0 = 0.f, q1 = 0.f;
            #pragma unroll
            for (int nt = 0; nt < 4; nt++) {
                float h0 = fmaxf(acc[nt][0], 0.f);
                float h1 = fmaxf(acc[nt][1], 0.f);
                float h2v = fmaxf(acc[nt][2], 0.f);
                float h3 = fmaxf(acc[nt][3], 0.f);
                p0 += h0 * wA[nt].x + h1 * wB[nt].x;
                p1 += h0 * wA[nt].y + h1 * wB[nt].y;
                q0 += h2v * wA[nt].x + h3 * wB[nt].x;
                q1 += h2v * wA[nt].y + h3 * wB[nt].y;
            }
            p0 += __shfl_xor_sync(0xffffffffu, p0, 1);
            p0 += __shfl_xor_sync(0xffffffffu, p0, 2);
            p1 += __shfl_xor_sync(0xffffffffu, p1, 1);
            p1 += __shfl_xor_sync(0xffffffffu, p1, 2);
            q0 += __shfl_xor_sync(0xffffffffu, q0, 1);
            q0 += __shfl_xor_sync(0xffffffffu, q0, 2);
            q1 += __shfl_xor_sync(0xffffffffu, q1, 1);
            q1 += __shfl_xor_sync(0xffffffffu, q1, 2);

            if (t == 0) {
                long long rr = base + tile * 16 + g;
                float2* ov = reinterpret_cast<float2*>(out);
                ov[rr]     = make_float2(p0 + bias0, p1 + bias1);
                ov[rr + 8] = make_float2(q0 + bias0, q1 + bias1);
            }
        }
    } else {
        // ================= scalar FFMA2 path (R3) =================
        int s_id = sg * 3 + (r - 13);
        long long blk0 = (long long)M_TOT + (long long)s_id * 1024;
        if (blk0 >= B) return;

        for (int i = threadIdx.x; i < NHID * 24; i += blockDim.x)
            sd[i] = g_const[(i / 24) * 12 + (i % 24) / 2];
        __syncthreads();

        long long s0 = blk0 + (long long)threadIdx.x * 4;
        if (s0 >= B) return;

        float bias0 = __ldg(&b2[0]);
        float bias1 = __ldg(&b2[1]);
        const ulonglong2* kp = reinterpret_cast<const ulonglong2*>(sd);

        if (s0 + 4 <= B) {
            const float4* xv = reinterpret_cast<const float4*>(x + s0 * 3);
            float4 XA = xv[0], XB = xv[1], XC = xv[2];
            float x0v[4] = { XA.x, XA.w, XB.z, XC.y };
            float x1v[4] = { XA.y, XB.x, XB.w, XC.z };

            float c0[4], sn0[4], c1[4], sn1[4];
            #pragma unroll
            for (int i = 0; i < 4; i++) {
                __sincosf(x0v[i], &sn0[i], &c0[i]);
                __sincosf(x1v[i], &sn1[i], &c1[i]);
            }

            u64 C0a = pk2(c0[0],  c0[1]),  C0b = pk2(c0[2],  c0[3]);
            u64 S0a = pk2(sn0[0], sn0[1]), S0b = pk2(sn0[2], sn0[3]);
            u64 C1a = pk2(c1[0],  c1[1]),  C1b = pk2(c1[2],  c1[3]);
            u64 S1a = pk2(sn1[0], sn1[1]), S1b = pk2(sn1[2], sn1[3]);

            u64 O0a = pk2(bias0, bias0), O1a = pk2(bias1, bias1);
            u64 O0b = O0a, O1b = O1a;

            #pragma unroll 4
            for (int j = 0; j < NHID; j++) {
                ulonglong2 q0 = kp[j*6+0], q1 = kp[j*6+1];
                ulonglong2 q2 = kp[j*6+2], q3 = kp[j*6+3];

                u64 t0a = ffma2(C1a, q0.y, q0.x);  t0a = ffma2(S1a, q1.x, t0a);
                u64 t1a = ffma2(C1a, q2.x, q1.y);  t1a = ffma2(S1a, q2.y, t1a);
                u64 t0b = ffma2(C1b, q0.y, q0.x);  t0b = ffma2(S1b, q1.x, t0b);
                u64 t1b = ffma2(C1b, q2.x, q1.y);  t1b = ffma2(S1b, q2.y, t1b);

                ulonglong2 q4 = kp[j*6+4], q5 = kp[j*6+5];

                u64 t2a = ffma2(C1a, q3.y, q3.x);  t2a = ffma2(S1a, q4.x, t2a);
                u64 t2b = ffma2(C1b, q3.y, q3.x);  t2b = ffma2(S1b, q4.x, t2b);

                u64 ga = ffma2(C0a, t1a, t0a);  ga = ffma2(S0a, t2a, ga);
                u64 gb = ffma2(C0b, t1b, t0b);  gb = ffma2(S0b, t2b, gb);

                u64 ha = relu2(ga), hb = relu2(gb);

                O0a = ffma2(ha, q4.y, O0a);  O1a = ffma2(ha, q5.x, O1a);
                O0b = ffma2(hb, q4.y, O0b);  O1b = ffma2(hb, q5.x, O1b);
            }

            float r00, r01, r10, r11;
            upk2(O0a, r00, r10);
            upk2(O1a, r01, r11);
            float4 w0 = { r00, r01, r10, r11 };
            upk2(O0b, r00, r10);
            upk2(O1b, r01, r11);
            float4 w1 = { r00, r01, r10, r11 };
            float4* ov = reinterpret_cast<float4*>(out + s0 * 2);
            ov[0] = w0;
            ov[1] = w1;
        } else {
            for (long long s = s0; s < B; s++) {
                float xx0 = x[s * 3], xx1 = x[s * 3 + 1];
                float cc0, ss0, cc1, ss1;
                __sincosf(xx0, &ss0, &cc0);
                __sincosf(xx1, &ss1, &cc1);
                float o0 = bias0, o1 = bias1;
                for (int j = 0; j < NHID; j++) {
                    const float* K = &sd[j * 24];
                    float t0 = K[0]  + K[2]*cc1  + K[4]*ss1;
                    float t1 = K[6]  + K[8]*cc1  + K[10]*ss1;
                    float t2 = K[12] + K[14]*cc1 + K[16]*ss1;
                    float h = fmaxf(t0 + cc0*t1 + ss0*t2, 0.f);
                    o0 += h * K[18];
                    o1 += h * K[20];
                }
                out[s * 2]     = o0;
                out[s * 2 + 1] = o1;
            }
        }
    }
}

extern "C" void kernel_launch(void* const* d_in, const int* in_sizes, int n_in,
                              void* d_out, int out_size)
{
    const float* x     = (const float*)d_in[0];
    const float* theta = (const float*)d_in[1];
    const float* W1    = (const float*)d_in[2];
    const float* b1    = (const float*)d_in[3];
    const float* W2    = (const float*)d_in[4];
    const float* b2    = (const float*)d_in[5];
    int B = in_sizes[0] / 3;

    setup_kernel<<<1, 32>>>(theta, W1, b1, W2);

    // split: ~52% of samples to the MMA path (multiple of 256)
    long long m_tot = ((long long)B * 52 / 100) / 256 * 256;
    int m_blocks = (int)(m_tot / 256);
    int n_super  = (m_blocks + 12) / 13;
    while ((long long)3 * n_super * 1024 < (long long)B - m_tot) n_super++;
    if (n_super < 1) n_super = 1;
    int nblocks = n_super * 16;

    qmlp_hybrid<<<nblocks, 256>>>(x, W2, b2, (float*)d_out, B, (int)m_tot);
}

// round 8
// speedup vs baseline: 1.1594x; 1.1594x over previous
#include <cuda_runtime.h>
#include <cuda_fp16.h>

#define NHID 32

// fp32 folded coefficients (tail path): per j: 9 K coeffs + W2[j][0..1] + pad
__device__ float g_const[NHID * 12];
// B fragments for mma.sync.m16n8k16: [kstep][ntile][reg][lane]
// KK rows: 0-8 = K_hi, 9-17 = K_hi (x F_lo), 18-26 = K_lo (x F_hi), 27-31 = 0.
__device__ unsigned int g_Bfrag[2][4][2][32];

struct cpx { float x, y; };

__device__ __forceinline__ void apply1q(cpx* s, cpx m00, cpx m01, cpx m10, cpx m11, int wire)
{
    int st = 1 << (2 - wire);
    for (int i = 0; i < 8; i++) {
        if (i & st) continue;
        cpx a = s[i], b = s[i + st];
        cpx n0 = { m00.x*a.x - m00.y*a.y + m01.x*b.x - m01.y*b.y,
                   m00.x*a.y + m00.y*a.x + m01.x*b.y + m01.y*b.x };
        cpx n1 = { m10.x*a.x - m10.y*a.y + m11.x*b.x - m11.y*b.y,
                   m10.x*a.y + m10.y*a.x + m11.x*b.y + m11.y*b.x };
        s[i] = n0; s[i + st] = n1;
    }
}

__device__ __forceinline__ void applyCRX(cpx* s, float c, float sn, int ctrl, int tgt)
{
    int cs = 1 << (2 - ctrl), ts = 1 << (2 - tgt);
    for (int i = 0; i < 8; i++) {
        if (!(i & cs) || (i & ts)) continue;
        cpx a = s[i], b = s[i + ts];
        s[i]      = { c*a.x + sn*b.y, c*a.y - sn*b.x };
        s[i + ts] = { c*b.x + sn*a.y, c*b.y - sn*a.x };
    }
}

__global__ void setup_kernel(const float* __restrict__ theta,
                             const float* __restrict__ W1,
                             const float* __restrict__ b1,
                             const float* __restrict__ W2)
{
    __shared__ cpx Vs[4][8];
    int tid = threadIdx.x;

    if (tid < 4) {
        cpx s[8];
        for (int i = 0; i < 8; i++) s[i] = {0.f, 0.f};
        s[tid * 2] = {1.f, 0.f};
        float c, sn;
        sincosf(0.5f * theta[0], &sn, &c);
        apply1q(s, {c,0.f},{0.f,-sn},{0.f,-sn},{c,0.f}, 0);
        sincosf(0.5f * theta[1], &sn, &c);
        apply1q(s, {c,0.f},{-sn,0.f},{sn,0.f},{c,0.f}, 1);
        sincosf(0.5f * theta[2], &sn, &c);
        apply1q(s, {c,-sn},{0.f,0.f},{0.f,0.f},{c,sn}, 2);
        sincosf(0.5f * theta[3], &sn, &c);
        applyCRX(s, c, sn, 0, 1);
        sincosf(0.5f * theta[4], &sn, &c);
        apply1q(s, {c,0.f},{-sn,0.f},{sn,0.f},{c,0.f}, 2);
        sincosf(0.5f * theta[5], &sn, &c);
        apply1q(s, {c,0.f},{0.f,-sn},{0.f,-sn},{c,0.f}, 1);
        sincosf(0.5f * theta[6], &sn, &c);
        applyCRX(s, c, sn, 1, 2);
        sincosf(0.5f * theta[7], &sn, &c);
        apply1q(s, {c,-sn},{0.f,0.f},{0.f,0.f},{c,sn}, 0);
        for (int k = 0; k < 8; k++)
            Vs[tid][k] = (tid >= 2) ? cpx{ s[k].y, -s[k].x } : s[k]; // * (-i)
    }
    __syncwarp();

    int j = tid;
    float M[4][4];
    for (int a = 0; a < 4; a++)
        for (int b = 0; b < 4; b++) {
            float m = 0.f;
            for (int k = 0; k < 8; k++)
                m += W1[k * NHID + j] * (Vs[a][k].x * Vs[b][k].x + Vs[a][k].y * Vs[b][k].y);
            M[a][b] = m;
        }

    const float R[2][2][3] = { { {0.5f, 0.5f, 0.f}, {0.f, 0.f, 0.5f} },
                               { {0.f, 0.f, 0.5f}, {0.5f, -0.5f, 0.f} } };
    float K[3][3] = { {0.f,0.f,0.f},{0.f,0.f,0.f},{0.f,0.f,0.f} };
    for (int a = 0; a < 4; a++)
        for (int b = 0; b < 4; b++) {
            int ia = a >> 1, ja = a & 1, ib = b >> 1, jb = b & 1;
            float Mab = M[a][b];
            for (int m = 0; m < 3; m++)
                for (int n = 0; n < 3; n++)
                    K[m][n] += Mab * R[ia][ib][m] * R[ja][jb][n];
        }
    K[0][0] += b1[j];

    float cf[9];
    for (int t = 0; t < 9; t++) cf[t] = K[t / 3][t % 3];

    for (int t = 0; t < 9; t++) g_const[j * 12 + t] = cf[t];
    g_const[j * 12 + 9]  = W2[j * 2 + 0];
    g_const[j * 12 + 10] = W2[j * 2 + 1];
    g_const[j * 12 + 11] = 0.f;

    float chi[9], clo[9];
    for (int i = 0; i < 9; i++) {
        chi[i] = __half2float(__float2half_rn(cf[i]));
        clo[i] = cf[i] - chi[i];
    }
    int nt = j >> 3, g = j & 7;
    for (int ks = 0; ks < 2; ks++)
        for (int r = 0; r < 2; r++)
            for (int t = 0; t < 4; t++) {
                int r0 = ks * 16 + 2 * t + r * 8;
                #define KKROW(rr) ((rr) < 9 ? chi[(rr)] : (rr) < 18 ? chi[(rr)-9] : (rr) < 27 ? clo[(rr)-18] : 0.f)
                float v0 = KKROW(r0);
                float v1 = KKROW(r0 + 1);
                #undef KKROW
                __half2 h2 = __floats2half2_rn(v0, v1);
                g_Bfrag[ks][nt][r][g * 4 + t] = *reinterpret_cast<unsigned int*>(&h2);
            }
}

__device__ __forceinline__ void mma16816(float c[4],
                                         unsigned a0, unsigned a1, unsigned a2, unsigned a3,
                                         unsigned b0, unsigned b1)
{
    asm volatile(
        "mma.sync.aligned.m16n8k16.row.col.f32.f16.f16.f32 "
        "{%0,%1,%2,%3}, {%4,%5,%6,%7}, {%8,%9}, {%0,%1,%2,%3};"
        : "+f"(c[0]), "+f"(c[1]), "+f"(c[2]), "+f"(c[3])
        : "r"(a0), "r"(a1), "r"(a2), "r"(a3), "r"(b0), "r"(b1));
}

// One warp = 64 samples = two 32-sample iterations sharing all uniform
// operands. A staged via smem (40-half row stride: conflict-free), x loaded
// via float4 + smem transpose.
__global__ void __launch_bounds__(256)
qmlp_mma(const float* __restrict__ x,
         const float* __restrict__ W2,
         const float* __restrict__ b2,
         float* __restrict__ out, int B)
{
    __shared__ __align__(16) __half sA[8][32 * 40];
    __shared__ __align__(16) float  sX[8][96];

    int lane = threadIdx.x & 31;
    int warp = threadIdx.x >> 5;
    long long G = (long long)blockIdx.x * 8 + warp;
    long long wbase = G * 64;
    if (wbase >= B) return;

    int g = lane >> 2, t = lane & 3;

    // ---- uniform operands, hoisted over both iterations ----
    unsigned bf[2][4][2];
    #pragma unroll
    for (int ks = 0; ks < 2; ks++)
        #pragma unroll
        for (int nt = 0; nt < 4; nt++) {
            bf[ks][nt][0] = __ldg(&g_Bfrag[ks][nt][0][lane]);
            bf[ks][nt][1] = __ldg(&g_Bfrag[ks][nt][1][lane]);
        }
    float2 wA[4], wB[4];
    #pragma unroll
    for (int nt = 0; nt < 4; nt++) {
        int j0 = nt * 8 + 2 * t;
        wA[nt] = __ldg(reinterpret_cast<const float2*>(W2 + (size_t)j0 * 2));
        wB[nt] = __ldg(reinterpret_cast<const float2*>(W2 + (size_t)(j0 + 1) * 2));
    }
    float bias0 = __ldg(&b2[0]);
    float bias1 = __ldg(&b2[1]);

    #pragma unroll
    for (int it = 0; it < 2; it++) {
        long long base = wbase + (long long)it * 32;
        if (base >= B) break;

        if (base + 32 <= B) {
            // ---- x via float4 + smem transpose (coalesced, conflict-free) ----
            const float4* xg = reinterpret_cast<const float4*>(x + base * 3);
            __syncwarp();
            if (lane < 24)
                reinterpret_cast<float4*>(sX[warp])[lane] = xg[lane];
            __syncwarp();
            float xa = sX[warp][lane * 3];
            float xb = sX[warp][lane * 3 + 1];   // x[...+2] is a global phase

            float s0n, c0n, s1n, c1n;
            __sincosf(xa, &s0n, &c0n);
            __sincosf(xb, &s1n, &c1n);
            float F[9] = { 1.f, c1n, s1n, c0n, c0n*c1n, c0n*s1n, s0n, s0n*c1n, s0n*s1n };
            float lo[9];
            #pragma unroll
            for (int i = 0; i < 9; i++)
                lo[i] = F[i] - __half2float(__float2half_rn(F[i]));

            // A row (32 halves): cols 0-8 F_hi, 9-17 F_lo, 18-26 F_hi, 27-31 0.
            unsigned w[16];
            __half2 h2;
            #define PACK(a, b) (h2 = __floats2half2_rn((a), (b)), *reinterpret_cast<unsigned*>(&h2))
            w[0]  = PACK(F[0], F[1]);
            w[1]  = PACK(F[2], F[3]);
            w[2]  = PACK(F[4], F[5]);
            w[3]  = PACK(F[6], F[7]);
            w[4]  = PACK(F[8], lo[0]);
            w[5]  = PACK(lo[1], lo[2]);
            w[6]  = PACK(lo[3], lo[4]);
            w[7]  = PACK(lo[5], lo[6]);
            w[8]  = PACK(lo[7], lo[8]);
            w[9]  = w[0]; w[10] = w[1]; w[11] = w[2]; w[12] = w[3];
            w[13] = PACK(F[8], 0.f);
            w[14] = 0u; w[15] = 0u;
            #undef PACK

            uint4* rp = reinterpret_cast<uint4*>(&sA[warp][lane * 40]);
            rp[0] = make_uint4(w[0],  w[1],  w[2],  w[3]);
            rp[1] = make_uint4(w[4],  w[5],  w[6],  w[7]);
            rp[2] = make_uint4(w[8],  w[9],  w[10], w[11]);
            rp[3] = make_uint4(w[12], w[13], w[14], w[15]);
            __syncwarp();

            const unsigned* sw = reinterpret_cast<const unsigned*>(sA[warp]);  // 20 words/row

            #pragma unroll
            for (int tile = 0; tile < 2; tile++) {
                float acc[4][4];
                #pragma unroll
                for (int nt = 0; nt < 4; nt++)
                    #pragma unroll
                    for (int c = 0; c < 4; c++) acc[nt][c] = 0.f;

                int r0w = (tile * 16 + g) * 20;
                int r1w = (tile * 16 + g + 8) * 20;
                #pragma unroll
                for (int ks = 0; ks < 2; ks++) {
                    unsigned a0 = sw[r0w + ks * 8 + t];
                    unsigned a1 = sw[r1w + ks * 8 + t];
                    unsigned a2 = sw[r0w + ks * 8 + t + 4];
                    unsigned a3 = sw[r1w + ks * 8 + t + 4];
                    #pragma unroll
                    for (int nt = 0; nt < 4; nt++)
                        mma16816(acc[nt], a0, a1, a2, a3, bf[ks][nt][0], bf[ks][nt][1]);
                }

                float p0 = 0.f, p1 = 0.f, q0 = 0.f, q1 = 0.f;
                #pragma unroll
                for (int nt = 0; nt < 4; nt++) {
                    float h0 = fmaxf(acc[nt][0], 0.f);
                    float h1 = fmaxf(acc[nt][1], 0.f);
                    float h2v = fmaxf(acc[nt][2], 0.f);
                    float h3 = fmaxf(acc[nt][3], 0.f);
                    p0 += h0 * wA[nt].x + h1 * wB[nt].x;
                    p1 += h0 * wA[nt].y + h1 * wB[nt].y;
                    q0 += h2v * wA[nt].x + h3 * wB[nt].x;
                    q1 += h2v * wA[nt].y + h3 * wB[nt].y;
                }
                p0 += __shfl_xor_sync(0xffffffffu, p0, 1);
                p0 += __shfl_xor_sync(0xffffffffu, p0, 2);
                p1 += __shfl_xor_sync(0xffffffffu, p1, 1);
                p1 += __shfl_xor_sync(0xffffffffu, p1, 2);
                q0 += __shfl_xor_sync(0xffffffffu, q0, 1);
                q0 += __shfl_xor_sync(0xffffffffu, q0, 2);
                q1 += __shfl_xor_sync(0xffffffffu, q1, 1);
                q1 += __shfl_xor_sync(0xffffffffu, q1, 2);

                if (t == 0) {
                    long long rr = base + tile * 16 + g;
                    float2* ov = reinterpret_cast<float2*>(out);
                    ov[rr]     = make_float2(p0 + bias0, p1 + bias1);
                    ov[rr + 8] = make_float2(q0 + bias0, q1 + bias1);
                }
            }
        } else {
            // scalar fp32 tail
            for (long long s = base + lane; s < B; s += 32) {
                float xx0 = x[s * 3], xx1 = x[s * 3 + 1];
                float cc0, ss0, cc1, ss1;
                __sincosf(xx0, &ss0, &cc0);
                __sincosf(xx1, &ss1, &cc1);
                float o0 = bias0, o1 = bias1;
                for (int j = 0; j < NHID; j++) {
                    const float* K = &g_const[j * 12];
                    float t0 = K[0] + K[1]*cc1 + K[2]*ss1;
                    float t1 = K[3] + K[4]*cc1 + K[5]*ss1;
                    float t2 = K[6] + K[7]*cc1 + K[8]*ss1;
                    float h = fmaxf(t0 + cc0*t1 + ss0*t2, 0.f);
                    o0 += h * K[9];
                    o1 += h * K[10];
                }
                out[s * 2]     = o0;
                out[s * 2 + 1] = o1;
            }
            break;
        }
    }
}

extern "C" void kernel_launch(void* const* d_in, const int* in_sizes, int n_in,
                              void* d_out, int out_size)
{
    const float* x     = (const float*)d_in[0];
    const float* theta = (const float*)d_in[1];
    const float* W1    = (const float*)d_in[2];
    const float* b1    = (const float*)d_in[3];
    const float* W2    = (const float*)d_in[4];
    const float* b2    = (const float*)d_in[5];
    int B = in_sizes[0] / 3;

    setup_kernel<<<1, 32>>>(theta, W1, b1, W2);

    long long wgroups = ((long long)B + 63) / 64;
    int nblocks = (int)((wgroups + 7) / 8);
    qmlp_mma<<<nblocks, 256>>>(x, W2, b2, (float*)d_out, B);
}

// round 9
// speedup vs baseline: 1.3928x; 1.2013x over previous
#include <cuda_runtime.h>
#include <cuda_fp16.h>

#define NHID 32

// fp32 folded coefficients (tail path): per j: 9 K coeffs + W2[j][0..1] + pad
__device__ float g_const[NHID * 12];
// Main-GEMM B fragments for mma.sync.m16n8k16: [kstep][ntile][reg][lane]
// KK rows: 0-8 = K_hi, 9-17 = K_hi (x F_lo), 18-26 = K_lo (x F_hi), 27-31 = 0.
__device__ unsigned int g_Bfrag[2][4][2][32];
// Epilogue B2 fragments: [kstep][reg][lane]. B2 is 16x8 (k=hidden, n=8):
// n 0,1 = f16(W2[:,n]); n 2,3 = f16((W2[:,n-2] - f16(W2[:,n-2])) * 4096); n>=4 = 0.
__device__ unsigned int g_B2frag[2][2][32];

struct cpx { float x, y; };

__device__ __forceinline__ void apply1q(cpx* s, cpx m00, cpx m01, cpx m10, cpx m11, int wire)
{
    int st = 1 << (2 - wire);
    for (int i = 0; i < 8; i++) {
        if (i & st) continue;
        cpx a = s[i], b = s[i + st];
        cpx n0 = { m00.x*a.x - m00.y*a.y + m01.x*b.x - m01.y*b.y,
                   m00.x*a.y + m00.y*a.x + m01.x*b.y + m01.y*b.x };
        cpx n1 = { m10.x*a.x - m10.y*a.y + m11.x*b.x - m11.y*b.y,
                   m10.x*a.y + m10.y*a.x + m11.x*b.y + m11.y*b.x };
        s[i] = n0; s[i + st] = n1;
    }
}

__device__ __forceinline__ void applyCRX(cpx* s, float c, float sn, int ctrl, int tgt)
{
    int cs = 1 << (2 - ctrl), ts = 1 << (2 - tgt);
    for (int i = 0; i < 8; i++) {
        if (!(i & cs) || (i & ts)) continue;
        cpx a = s[i], b = s[i + ts];
        s[i]      = { c*a.x + sn*b.y, c*a.y - sn*b.x };
        s[i + ts] = { c*b.x + sn*a.y, c*b.y - sn*a.x };
    }
}

__global__ void setup_kernel(const float* __restrict__ theta,
                             const float* __restrict__ W1,
                             const float* __restrict__ b1,
                             const float* __restrict__ W2)
{
    __shared__ cpx Vs[4][8];
    int tid = threadIdx.x;

    if (tid < 4) {
        cpx s[8];
        for (int i = 0; i < 8; i++) s[i] = {0.f, 0.f};
        s[tid * 2] = {1.f, 0.f};
        float c, sn;
        sincosf(0.5f * theta[0], &sn, &c);
        apply1q(s, {c,0.f},{0.f,-sn},{0.f,-sn},{c,0.f}, 0);
        sincosf(0.5f * theta[1], &sn, &c);
        apply1q(s, {c,0.f},{-sn,0.f},{sn,0.f},{c,0.f}, 1);
        sincosf(0.5f * theta[2], &sn, &c);
        apply1q(s, {c,-sn},{0.f,0.f},{0.f,0.f},{c,sn}, 2);
        sincosf(0.5f * theta[3], &sn, &c);
        applyCRX(s, c, sn, 0, 1);
        sincosf(0.5f * theta[4], &sn, &c);
        apply1q(s, {c,0.f},{-sn,0.f},{sn,0.f},{c,0.f}, 2);
        sincosf(0.5f * theta[5], &sn, &c);
        apply1q(s, {c,0.f},{0.f,-sn},{0.f,-sn},{c,0.f}, 1);
        sincosf(0.5f * theta[6], &sn, &c);
        applyCRX(s, c, sn, 1, 2);
        sincosf(0.5f * theta[7], &sn, &c);
        apply1q(s, {c,-sn},{0.f,0.f},{0.f,0.f},{c,sn}, 0);
        for (int k = 0; k < 8; k++)
            Vs[tid][k] = (tid >= 2) ? cpx{ s[k].y, -s[k].x } : s[k]; // * (-i)
    }
    __syncwarp();

    int j = tid;
    float M[4][4];
    for (int a = 0; a < 4; a++)
        for (int b = 0; b < 4; b++) {
            float m = 0.f;
            for (int k = 0; k < 8; k++)
                m += W1[k * NHID + j] * (Vs[a][k].x * Vs[b][k].x + Vs[a][k].y * Vs[b][k].y);
            M[a][b] = m;
        }

    const float R[2][2][3] = { { {0.5f, 0.5f, 0.f}, {0.f, 0.f, 0.5f} },
                               { {0.f, 0.f, 0.5f}, {0.5f, -0.5f, 0.f} } };
    float K[3][3] = { {0.f,0.f,0.f},{0.f,0.f,0.f},{0.f,0.f,0.f} };
    for (int a = 0; a < 4; a++)
        for (int b = 0; b < 4; b++) {
            int ia = a >> 1, ja = a & 1, ib = b >> 1, jb = b & 1;
            float Mab = M[a][b];
            for (int m = 0; m < 3; m++)
                for (int n = 0; n < 3; n++)
                    K[m][n] += Mab * R[ia][ib][m] * R[ja][jb][n];
        }
    K[0][0] += b1[j];

    float cf[9];
    for (int t = 0; t < 9; t++) cf[t] = K[t / 3][t % 3];

    for (int t = 0; t < 9; t++) g_const[j * 12 + t] = cf[t];
    g_const[j * 12 + 9]  = W2[j * 2 + 0];
    g_const[j * 12 + 10] = W2[j * 2 + 1];
    g_const[j * 12 + 11] = 0.f;

    // main-GEMM fragments (split-f16 K)
    float chi[9], clo[9];
    for (int i = 0; i < 9; i++) {
        chi[i] = __half2float(__float2half_rn(cf[i]));
        clo[i] = cf[i] - chi[i];
    }
    {
        int nt = j >> 3, g = j & 7;
        for (int ks = 0; ks < 2; ks++)
            for (int r = 0; r < 2; r++)
                for (int t = 0; t < 4; t++) {
                    int r0 = ks * 16 + 2 * t + r * 8;
                    #define KKROW(rr) ((rr) < 9 ? chi[(rr)] : (rr) < 18 ? chi[(rr)-9] : (rr) < 27 ? clo[(rr)-18] : 0.f)
                    float v0 = KKROW(r0);
                    float v1 = KKROW(r0 + 1);
                    #undef KKROW
                    __half2 h2 = __floats2half2_rn(v0, v1);
                    g_Bfrag[ks][nt][r][g * 4 + t] = *reinterpret_cast<unsigned int*>(&h2);
                }
    }

    // epilogue B2 fragments: lane = tid, g = lane>>2 (n index), t = lane&3
    {
        int g = tid >> 2, t = tid & 3;
        for (int ks = 0; ks < 2; ks++)
            for (int r = 0; r < 2; r++) {
                int k0 = ks * 16 + 2 * t + r * 8;   // hidden row index
                float v0 = 0.f, v1 = 0.f;
                if (g < 2) {
                    v0 = W2[k0 * 2 + g];
                    v1 = W2[(k0 + 1) * 2 + g];
                } else if (g < 4) {
                    int c = g - 2;
                    float w0f = W2[k0 * 2 + c];
                    float w1f = W2[(k0 + 1) * 2 + c];
                    v0 = (w0f - __half2float(__float2half_rn(w0f))) * 4096.f;
                    v1 = (w1f - __half2float(__float2half_rn(w1f))) * 4096.f;
                }
                __half2 h2 = __floats2half2_rn(v0, v1);
                g_B2frag[ks][r][tid] = *reinterpret_cast<unsigned int*>(&h2);
            }
    }
}

__device__ __forceinline__ void mma16816(float c[4],
                                         unsigned a0, unsigned a1, unsigned a2, unsigned a3,
                                         unsigned b0, unsigned b1)
{
    asm volatile(
        "mma.sync.aligned.m16n8k16.row.col.f32.f16.f16.f32 "
        "{%0,%1,%2,%3}, {%4,%5,%6,%7}, {%8,%9}, {%0,%1,%2,%3};"
        : "+f"(c[0]), "+f"(c[1]), "+f"(c[2]), "+f"(c[3])
        : "r"(a0), "r"(a1), "r"(a2), "r"(a3), "r"(b0), "r"(b1));
}

// One warp = 32 samples. Hidden layer: split-f16 MMA (exact). Output layer:
// MMA on f16(relu(H)) with exact W2 via scaled-lo n-columns.
__global__ void __launch_bounds__(256)
qmlp_mma(const float* __restrict__ x,
         const float* __restrict__ b2,
         float* __restrict__ out, int B)
{
    __shared__ __align__(16) __half sA[8][32 * 40];

    int lane = threadIdx.x & 31;
    int warp = threadIdx.x >> 5;
    long long G = (long long)blockIdx.x * 8 + warp;
    long long base = G * 32;
    if (base >= B) return;

    int g = lane >> 2, t = lane & 3;
    float bias0 = __ldg(&b2[0]);
    float bias1 = __ldg(&b2[1]);

    if (base + 32 <= B) {
        // hoisted uniform fragments
        unsigned bf[2][4][2];
        #pragma unroll
        for (int ks = 0; ks < 2; ks++)
            #pragma unroll
            for (int nt = 0; nt < 4; nt++) {
                bf[ks][nt][0] = __ldg(&g_Bfrag[ks][nt][0][lane]);
                bf[ks][nt][1] = __ldg(&g_Bfrag[ks][nt][1][lane]);
            }
        unsigned b2f[2][2];
        #pragma unroll
        for (int ks = 0; ks < 2; ks++) {
            b2f[ks][0] = __ldg(&g_B2frag[ks][0][lane]);
            b2f[ks][1] = __ldg(&g_B2frag[ks][1][lane]);
        }

        // per-lane feature row (sample = base + lane)
        long long S = base + lane;
        float xa = __ldg(&x[S * 3]);
        float xb = __ldg(&x[S * 3 + 1]);      // x[...+2] is a global phase
        float s0n, c0n, s1n, c1n;
        __sincosf(xa, &s0n, &c0n);
        __sincosf(xb, &s1n, &c1n);
        float F[9] = { 1.f, c1n, s1n, c0n, c0n*c1n, c0n*s1n, s0n, s0n*c1n, s0n*s1n };
        float lo[9];
        #pragma unroll
        for (int i = 0; i < 9; i++)
            lo[i] = F[i] - __half2float(__float2half_rn(F[i]));

        // A row (32 halves): cols 0-8 F_hi, 9-17 F_lo, 18-26 F_hi, 27-31 0.
        unsigned w[16];
        __half2 h2;
        #define PACK(a, b) (h2 = __floats2half2_rn((a), (b)), *reinterpret_cast<unsigned*>(&h2))
        w[0]  = PACK(F[0], F[1]);
        w[1]  = PACK(F[2], F[3]);
        w[2]  = PACK(F[4], F[5]);
        w[3]  = PACK(F[6], F[7]);
        w[4]  = PACK(F[8], lo[0]);
        w[5]  = PACK(lo[1], lo[2]);
        w[6]  = PACK(lo[3], lo[4]);
        w[7]  = PACK(lo[5], lo[6]);
        w[8]  = PACK(lo[7], lo[8]);
        w[9]  = w[0]; w[10] = w[1]; w[11] = w[2]; w[12] = w[3];
        w[13] = PACK(F[8], 0.f);
        w[14] = 0u; w[15] = 0u;
        #undef PACK

        uint4* rp = reinterpret_cast<uint4*>(&sA[warp][lane * 40]);
        rp[0] = make_uint4(w[0],  w[1],  w[2],  w[3]);
        rp[1] = make_uint4(w[4],  w[5],  w[6],  w[7]);
        rp[2] = make_uint4(w[8],  w[9],  w[10], w[11]);
        rp[3] = make_uint4(w[12], w[13], w[14], w[15]);
        __syncwarp();

        const unsigned* sw = reinterpret_cast<const unsigned*>(sA[warp]);  // 20 words/row
        const __half2 hz = __floats2half2_rn(0.f, 0.f);
        const float SCL = 1.f / 4096.f;

        #pragma unroll
        for (int tile = 0; tile < 2; tile++) {
            float acc[4][4];
            #pragma unroll
            for (int nt = 0; nt < 4; nt++)
                #pragma unroll
                for (int c = 0; c < 4; c++) acc[nt][c] = 0.f;

            int r0w = (tile * 16 + g) * 20;
            int r1w = (tile * 16 + g + 8) * 20;
            #pragma unroll
            for (int ks = 0; ks < 2; ks++) {
                unsigned a0 = sw[r0w + ks * 8 + t];
                unsigned a1 = sw[r1w + ks * 8 + t];
                unsigned a2 = sw[r0w + ks * 8 + t + 4];
                unsigned a3 = sw[r1w + ks * 8 + t + 4];
                #pragma unroll
                for (int nt = 0; nt < 4; nt++)
                    mma16816(acc[nt], a0, a1, a2, a3, bf[ks][nt][0], bf[ks][nt][1]);
            }

            // ---- epilogue on the tensor pipe ----
            // H_hi = f16(relu(H)) fragments; D layout == A layout for next MMA.
            unsigned hp[4][2];
            #pragma unroll
            for (int nt = 0; nt < 4; nt++) {
                __half2 t01 = __floats2half2_rn(acc[nt][0], acc[nt][1]);
                __half2 t23 = __floats2half2_rn(acc[nt][2], acc[nt][3]);
                t01 = __hmax2(t01, hz);
                t23 = __hmax2(t23, hz);
                hp[nt][0] = *reinterpret_cast<unsigned*>(&t01);
                hp[nt][1] = *reinterpret_cast<unsigned*>(&t23);
            }
            float o[4] = { 0.f, 0.f, 0.f, 0.f };
            mma16816(o, hp[0][0], hp[0][1], hp[1][0], hp[1][1], b2f[0][0], b2f[0][1]);
            mma16816(o, hp[2][0], hp[2][1], hp[3][0], hp[3][1], b2f[1][0], b2f[1][1]);

            // t=0 lanes hold W2_hi result (n=0,1); t=1 lanes hold the scaled
            // W2_lo correction (n=2,3). Combine exactly.
            float cr0 = __shfl_xor_sync(0xffffffffu, o[0], 1);
            float cr1 = __shfl_xor_sync(0xffffffffu, o[1], 1);
            float cr2 = __shfl_xor_sync(0xffffffffu, o[2], 1);
            float cr3 = __shfl_xor_sync(0xffffffffu, o[3], 1);

            if (t == 0) {
                long long rr = base + tile * 16 + g;
                float2* ov = reinterpret_cast<float2*>(out);
                ov[rr]     = make_float2(fmaf(cr0, SCL, o[0]) + bias0,
                                         fmaf(cr1, SCL, o[1]) + bias1);
                ov[rr + 8] = make_float2(fmaf(cr2, SCL, o[2]) + bias0,
                                         fmaf(cr3, SCL, o[3]) + bias1);
            }
        }
    } else {
        // scalar fp32 tail
        for (long long s = base + lane; s < B; s += 32) {
            float xx0 = x[s * 3], xx1 = x[s * 3 + 1];
            float cc0, ss0, cc1, ss1;
            __sincosf(xx0, &ss0, &cc0);
            __sincosf(xx1, &ss1, &cc1);
            float o0 = bias0, o1 = bias1;
            for (int j = 0; j < NHID; j++) {
                const float* K = &g_const[j * 12];
                float t0 = K[0] + K[1]*cc1 + K[2]*ss1;
                float t1 = K[3] + K[4]*cc1 + K[5]*ss1;
                float t2 = K[6] + K[7]*cc1 + K[8]*ss1;
                float h = fmaxf(t0 + cc0*t1 + ss0*t2, 0.f);
                o0 += h * K[9];
                o1 += h * K[10];
            }
            out[s * 2]     = o0;
            out[s * 2 + 1] = o1;
        }
    }
}

extern "C" void kernel_launch(void* const* d_in, const int* in_sizes, int n_in,
                              void* d_out, int out_size)
{
    const float* x     = (const float*)d_in[0];
    const float* theta = (const float*)d_in[1];
    const float* W1    = (const float*)d_in[2];
    const float* b1    = (const float*)d_in[3];
    const float* W2    = (const float*)d_in[4];
    const float* b2    = (const float*)d_in[5];
    int B = in_sizes[0] / 3;

    setup_kernel<<<1, 32>>>(theta, W1, b1, W2);

    long long wgroups = ((long long)B + 31) / 32;
    int nblocks = (int)((wgroups + 7) / 8);
    qmlp_mma<<<nblocks, 256>>>(x, b2, (float*)d_out, B);
}

// round 10
// speedup vs baseline: 1.5094x; 1.0837x over previous
#include <cuda_runtime.h>
#include <cuda_fp16.h>

#define NHID 32

// fp32 folded coefficients (tail path): per j: 9 K coeffs + W2[j][0..1] + pad
__device__ float g_const[NHID * 12];
// Main-GEMM B fragments for mma.sync.m16n8k16: [kstep][ntile][reg][lane]
// KK rows: 0-8 = K_hi, 9-17 = K_hi (x F_lo), 18-26 = K_lo (x F_hi), 27-31 = 0.
__device__ unsigned int g_Bfrag[2][4][2][32];
// Epilogue B2 fragments: [kstep][reg][lane]. B2 is 16x8 (k=hidden, n=8):
// n 0,1 = f16(W2[:,n]); n 2,3 = f16((W2[:,n-2] - f16(W2[:,n-2])) * 4096); n>=4 = 0.
__device__ unsigned int g_B2frag[2][2][32];

struct cpx { float x, y; };

__device__ __forceinline__ void apply1q(cpx* s, cpx m00, cpx m01, cpx m10, cpx m11, int wire)
{
    int st = 1 << (2 - wire);
    for (int i = 0; i < 8; i++) {
        if (i & st) continue;
        cpx a = s[i], b = s[i + st];
        cpx n0 = { m00.x*a.x - m00.y*a.y + m01.x*b.x - m01.y*b.y,
                   m00.x*a.y + m00.y*a.x + m01.x*b.y + m01.y*b.x };
        cpx n1 = { m10.x*a.x - m10.y*a.y + m11.x*b.x - m11.y*b.y,
                   m10.x*a.y + m10.y*a.x + m11.x*b.y + m11.y*b.x };
        s[i] = n0; s[i + st] = n1;
    }
}

__device__ __forceinline__ void applyCRX(cpx* s, float c, float sn, int ctrl, int tgt)
{
    int cs = 1 << (2 - ctrl), ts = 1 << (2 - tgt);
    for (int i = 0; i < 8; i++) {
        if (!(i & cs) || (i & ts)) continue;
        cpx a = s[i], b = s[i + ts];
        s[i]      = { c*a.x + sn*b.y, c*a.y - sn*b.x };
        s[i + ts] = { c*b.x + sn*a.y, c*b.y - sn*a.x };
    }
}

__global__ void setup_kernel(const float* __restrict__ theta,
                             const float* __restrict__ W1,
                             const float* __restrict__ b1,
                             const float* __restrict__ W2)
{
    __shared__ cpx Vs[4][8];
    int tid = threadIdx.x;

    if (tid < 4) {
        cpx s[8];
        for (int i = 0; i < 8; i++) s[i] = {0.f, 0.f};
        s[tid * 2] = {1.f, 0.f};
        float c, sn;
        sincosf(0.5f * theta[0], &sn, &c);
        apply1q(s, {c,0.f},{0.f,-sn},{0.f,-sn},{c,0.f}, 0);
        sincosf(0.5f * theta[1], &sn, &c);
        apply1q(s, {c,0.f},{-sn,0.f},{sn,0.f},{c,0.f}, 1);
        sincosf(0.5f * theta[2], &sn, &c);
        apply1q(s, {c,-sn},{0.f,0.f},{0.f,0.f},{c,sn}, 2);
        sincosf(0.5f * theta[3], &sn, &c);
        applyCRX(s, c, sn, 0, 1);
        sincosf(0.5f * theta[4], &sn, &c);
        apply1q(s, {c,0.f},{-sn,0.f},{sn,0.f},{c,0.f}, 2);
        sincosf(0.5f * theta[5], &sn, &c);
        apply1q(s, {c,0.f},{0.f,-sn},{0.f,-sn},{c,0.f}, 1);
        sincosf(0.5f * theta[6], &sn, &c);
        applyCRX(s, c, sn, 1, 2);
        sincosf(0.5f * theta[7], &sn, &c);
        apply1q(s, {c,-sn},{0.f,0.f},{0.f,0.f},{c,sn}, 0);
        for (int k = 0; k < 8; k++)
            Vs[tid][k] = (tid >= 2) ? cpx{ s[k].y, -s[k].x } : s[k]; // * (-i)
    }
    __syncwarp();

    int j = tid;
    float M[4][4];
    for (int a = 0; a < 4; a++)
        for (int b = 0; b < 4; b++) {
            float m = 0.f;
            for (int k = 0; k < 8; k++)
                m += W1[k * NHID + j] * (Vs[a][k].x * Vs[b][k].x + Vs[a][k].y * Vs[b][k].y);
            M[a][b] = m;
        }

    const float R[2][2][3] = { { {0.5f, 0.5f, 0.f}, {0.f, 0.f, 0.5f} },
                               { {0.f, 0.f, 0.5f}, {0.5f, -0.5f, 0.f} } };
    float K[3][3] = { {0.f,0.f,0.f},{0.f,0.f,0.f},{0.f,0.f,0.f} };
    for (int a = 0; a < 4; a++)
        for (int b = 0; b < 4; b++) {
            int ia = a >> 1, ja = a & 1, ib = b >> 1, jb = b & 1;
            float Mab = M[a][b];
            for (int m = 0; m < 3; m++)
                for (int n = 0; n < 3; n++)
                    K[m][n] += Mab * R[ia][ib][m] * R[ja][jb][n];
        }
    K[0][0] += b1[j];

    float cf[9];
    for (int t = 0; t < 9; t++) cf[t] = K[t / 3][t % 3];

    for (int t = 0; t < 9; t++) g_const[j * 12 + t] = cf[t];
    g_const[j * 12 + 9]  = W2[j * 2 + 0];
    g_const[j * 12 + 10] = W2[j * 2 + 1];
    g_const[j * 12 + 11] = 0.f;

    // main-GEMM fragments (split-f16 K)
    float chi[9], clo[9];
    for (int i = 0; i < 9; i++) {
        chi[i] = __half2float(__float2half_rn(cf[i]));
        clo[i] = cf[i] - chi[i];
    }
    {
        int nt = j >> 3, g = j & 7;
        for (int ks = 0; ks < 2; ks++)
            for (int r = 0; r < 2; r++)
                for (int t = 0; t < 4; t++) {
                    int r0 = ks * 16 + 2 * t + r * 8;
                    #define KKROW(rr) ((rr) < 9 ? chi[(rr)] : (rr) < 18 ? chi[(rr)-9] : (rr) < 27 ? clo[(rr)-18] : 0.f)
                    float v0 = KKROW(r0);
                    float v1 = KKROW(r0 + 1);
                    #undef KKROW
                    __half2 h2 = __floats2half2_rn(v0, v1);
                    g_Bfrag[ks][nt][r][g * 4 + t] = *reinterpret_cast<unsigned int*>(&h2);
                }
    }

    // epilogue B2 fragments
    {
        int g = tid >> 2, t = tid & 3;
        for (int ks = 0; ks < 2; ks++)
            for (int r = 0; r < 2; r++) {
                int k0 = ks * 16 + 2 * t + r * 8;
                float v0 = 0.f, v1 = 0.f;
                if (g < 2) {
                    v0 = W2[k0 * 2 + g];
                    v1 = W2[(k0 + 1) * 2 + g];
                } else if (g < 4) {
                    int c = g - 2;
                    float w0f = W2[k0 * 2 + c];
                    float w1f = W2[(k0 + 1) * 2 + c];
                    v0 = (w0f - __half2float(__float2half_rn(w0f))) * 4096.f;
                    v1 = (w1f - __half2float(__float2half_rn(w1f))) * 4096.f;
                }
                __half2 h2 = __floats2half2_rn(v0, v1);
                g_B2frag[ks][r][tid] = *reinterpret_cast<unsigned int*>(&h2);
            }
    }
}

__device__ __forceinline__ void mma16816(float c[4],
                                         unsigned a0, unsigned a1, unsigned a2, unsigned a3,
                                         unsigned b0, unsigned b1)
{
    asm volatile(
        "mma.sync.aligned.m16n8k16.row.col.f32.f16.f16.f32 "
        "{%0,%1,%2,%3}, {%4,%5,%6,%7}, {%8,%9}, {%0,%1,%2,%3};"
        : "+f"(c[0]), "+f"(c[1]), "+f"(c[2]), "+f"(c[3])
        : "r"(a0), "r"(a1), "r"(a2), "r"(a3), "r"(b0), "r"(b1));
}

__device__ __forceinline__ void ldmatrix_x4(unsigned& a0, unsigned& a1,
                                            unsigned& a2, unsigned& a3,
                                            unsigned saddr)
{
    asm volatile(
        "ldmatrix.sync.aligned.m8n8.x4.shared.b16 {%0,%1,%2,%3}, [%4];"
        : "=r"(a0), "=r"(a1), "=r"(a2), "=r"(a3) : "r"(saddr));
}

// One warp = 64 samples (2 iterations sharing uniform fragments).
// Hidden layer: split-f16 MMA (exact). Output layer: MMA on f16(relu(H))
// with exact W2 via scaled-lo n-columns. A loaded via ldmatrix.x4.
__global__ void __launch_bounds__(256, 4)
qmlp_mma(const float* __restrict__ x,
         const float* __restrict__ b2,
         float* __restrict__ out, int B)
{
    __shared__ __align__(16) __half sA[8][32 * 40];

    int lane = threadIdx.x & 31;
    int warp = threadIdx.x >> 5;
    long long G = (long long)blockIdx.x * 8 + warp;
    long long wbase = G * 64;
    if (wbase >= B) return;

    int g = lane >> 2, t = lane & 3;
    float bias0 = __ldg(&b2[0]);
    float bias1 = __ldg(&b2[1]);

    // hoisted uniform fragments (shared across both iterations)
    unsigned bf[2][4][2];
    #pragma unroll
    for (int ks = 0; ks < 2; ks++)
        #pragma unroll
        for (int nt = 0; nt < 4; nt++) {
            bf[ks][nt][0] = __ldg(&g_Bfrag[ks][nt][0][lane]);
            bf[ks][nt][1] = __ldg(&g_Bfrag[ks][nt][1][lane]);
        }
    unsigned b2f[2][2];
    #pragma unroll
    for (int ks = 0; ks < 2; ks++) {
        b2f[ks][0] = __ldg(&g_B2frag[ks][0][lane]);
        b2f[ks][1] = __ldg(&g_B2frag[ks][1][lane]);
    }

    // per-lane ldmatrix row address component (halves):
    // lanes 0-7: M0 rows, 8-15: M1 rows (+8), 16-23: M2 (k+8), 24-31: M3.
    int lm_row   = lane & 15;
    int lm_khalf = (lane >> 4) * 8;
    unsigned sbase = (unsigned)__cvta_generic_to_shared(&sA[warp][0]);

    const __half2 hz = __floats2half2_rn(0.f, 0.f);
    const float SCL = 1.f / 4096.f;

    #pragma unroll
    for (int it = 0; it < 2; it++) {
        long long base = wbase + (long long)it * 32;
        if (base >= B) break;

        if (base + 32 <= B) {
            long long S = base + lane;
            float xa = __ldg(&x[S * 3]);
            float xb = __ldg(&x[S * 3 + 1]);      // x[...+2] is a global phase
            float s0n, c0n, s1n, c1n;
            __sincosf(xa, &s0n, &c0n);
            __sincosf(xb, &s1n, &c1n);
            float F[9] = { 1.f, c1n, s1n, c0n, c0n*c1n, c0n*s1n, s0n, s0n*c1n, s0n*s1n };
            float lo[9];
            #pragma unroll
            for (int i = 0; i < 9; i++)
                lo[i] = F[i] - __half2float(__float2half_rn(F[i]));

            // A row (32 halves): cols 0-8 F_hi, 9-17 F_lo, 18-26 F_hi, 27-31 0.
            unsigned w[16];
            __half2 h2;
            #define PACK(a, b) (h2 = __floats2half2_rn((a), (b)), *reinterpret_cast<unsigned*>(&h2))
            w[0]  = PACK(F[0], F[1]);
            w[1]  = PACK(F[2], F[3]);
            w[2]  = PACK(F[4], F[5]);
            w[3]  = PACK(F[6], F[7]);
            w[4]  = PACK(F[8], lo[0]);
            w[5]  = PACK(lo[1], lo[2]);
            w[6]  = PACK(lo[3], lo[4]);
            w[7]  = PACK(lo[5], lo[6]);
            w[8]  = PACK(lo[7], lo[8]);
            w[9]  = w[0]; w[10] = w[1]; w[11] = w[2]; w[12] = w[3];
            w[13] = PACK(F[8], 0.f);
            w[14] = 0u; w[15] = 0u;
            #undef PACK

            __syncwarp();   // protect sA reuse across iterations
            uint4* rp = reinterpret_cast<uint4*>(&sA[warp][lane * 40]);
            rp[0] = make_uint4(w[0],  w[1],  w[2],  w[3]);
            rp[1] = make_uint4(w[4],  w[5],  w[6],  w[7]);
            rp[2] = make_uint4(w[8],  w[9],  w[10], w[11]);
            rp[3] = make_uint4(w[12], w[13], w[14], w[15]);
            __syncwarp();

            #pragma unroll
            for (int tile = 0; tile < 2; tile++) {
                float acc[4][4];
                #pragma unroll
                for (int nt = 0; nt < 4; nt++)
                    #pragma unroll
                    for (int c = 0; c < 4; c++) acc[nt][c] = 0.f;

                // A fragments via ldmatrix.x4 (one per k-step)
                unsigned lmaddr = sbase +
                    ((unsigned)(tile * 16 + lm_row) * 40u + (unsigned)lm_khalf) * 2u;
                #pragma unroll
                for (int ks = 0; ks < 2; ks++) {
                    unsigned a0, a1, a2, a3;
                    ldmatrix_x4(a0, a1, a2, a3, lmaddr + (unsigned)ks * 32u);
                    #pragma unroll
                    for (int nt = 0; nt < 4; nt++)
                        mma16816(acc[nt], a0, a1, a2, a3, bf[ks][nt][0], bf[ks][nt][1]);
                }

                // epilogue on the tensor pipe
                unsigned hp[4][2];
                #pragma unroll
                for (int nt = 0; nt < 4; nt++) {
                    __half2 t01 = __floats2half2_rn(acc[nt][0], acc[nt][1]);
                    __half2 t23 = __floats2half2_rn(acc[nt][2], acc[nt][3]);
                    t01 = __hmax2(t01, hz);
                    t23 = __hmax2(t23, hz);
                    hp[nt][0] = *reinterpret_cast<unsigned*>(&t01);
                    hp[nt][1] = *reinterpret_cast<unsigned*>(&t23);
                }
                float o[4] = { 0.f, 0.f, 0.f, 0.f };
                mma16816(o, hp[0][0], hp[0][1], hp[1][0], hp[1][1], b2f[0][0], b2f[0][1]);
                mma16816(o, hp[2][0], hp[2][1], hp[3][0], hp[3][1], b2f[1][0], b2f[1][1]);

                // t=0 lanes: W2_hi (n=0,1); t=1 lanes: scaled W2_lo (n=2,3).
                float cr0 = __shfl_xor_sync(0xffffffffu, o[0], 1);
                float cr1 = __shfl_xor_sync(0xffffffffu, o[1], 1);
                float cr2 = __shfl_xor_sync(0xffffffffu, o[2], 1);
                float cr3 = __shfl_xor_sync(0xffffffffu, o[3], 1);

                if (t == 0) {
                    long long rr = base + tile * 16 + g;
                    float2* ov = reinterpret_cast<float2*>(out);
                    ov[rr]     = make_float2(fmaf(cr0, SCL, o[0]) + bias0,
                                             fmaf(cr1, SCL, o[1]) + bias1);
                    ov[rr + 8] = make_float2(fmaf(cr2, SCL, o[2]) + bias0,
                                             fmaf(cr3, SCL, o[3]) + bias1);
                }
            }
        } else {
            // scalar fp32 tail
            for (long long s = base + lane; s < B; s += 32) {
                float xx0 = x[s * 3], xx1 = x[s * 3 + 1];
                float cc0, ss0, cc1, ss1;
                __sincosf(xx0, &ss0, &cc0);
                __sincosf(xx1, &ss1, &cc1);
                float o0 = bias0, o1 = bias1;
                for (int j = 0; j < NHID; j++) {
                    const float* K = &g_const[j * 12];
                    float t0 = K[0] + K[1]*cc1 + K[2]*ss1;
                    float t1 = K[3] + K[4]*cc1 + K[5]*ss1;
                    float t2 = K[6] + K[7]*cc1 + K[8]*ss1;
                    float h = fmaxf(t0 + cc0*t1 + ss0*t2, 0.f);
                    o0 += h * K[9];
                    o1 += h * K[10];
                }
                out[s * 2]     = o0;
                out[s * 2 + 1] = o1;
            }
            break;
        }
    }
}

extern "C" void kernel_launch(void* const* d_in, const int* in_sizes, int n_in,
                              void* d_out, int out_size)
{
    const float* x     = (const float*)d_in[0];
    const float* theta = (const float*)d_in[1];
    const float* W1    = (const float*)d_in[2];
    const float* b1    = (const float*)d_in[3];
    const float* W2    = (const float*)d_in[4];
    const float* b2    = (const float*)d_in[5];
    int B = in_sizes[0] / 3;

    setup_kernel<<<1, 32>>>(theta, W1, b1, W2);

    long long wgroups = ((long long)B + 63) / 64;
    int nblocks = (int)((wgroups + 7) / 8);
    qmlp_mma<<<nblocks, 256>>>(x, b2, (float*)d_out, B);
}

// round 12
// speedup vs baseline: 1.9306x; 1.2790x over previous
#include <cuda_runtime.h>
#include <cuda_fp16.h>

#define NHID 32

// fp32 folded coefficients (tail path): per j: 9 K coeffs + W2[j][0..1] + pad
__device__ float g_const[NHID * 12];
// Main-GEMM B fragments for mma.sync.m16n8k16 (single k-step):
// [ntile][reg][lane]; KK rows 0-8 = f16(K), rows 9-15 = 0.
__device__ unsigned int g_Bfrag[4][2][32];
// Epilogue B2 fragments: [kstep][reg][lane]. B2 is 16x8 (k=hidden, n=8):
// n 0,1 = f16(W2[:,n]); n 2,3 = f16((W2[:,n-2] - f16(W2[:,n-2])) * 4096); n>=4 = 0.
__device__ unsigned int g_B2frag[2][2][32];

struct cpx { float x, y; };

__device__ __forceinline__ void apply1q(cpx* s, cpx m00, cpx m01, cpx m10, cpx m11, int wire)
{
    int st = 1 << (2 - wire);
    for (int i = 0; i < 8; i++) {
        if (i & st) continue;
        cpx a = s[i], b = s[i + st];
        cpx n0 = { m00.x*a.x - m00.y*a.y + m01.x*b.x - m01.y*b.y,
                   m00.x*a.y + m00.y*a.x + m01.x*b.y + m01.y*b.x };
        cpx n1 = { m10.x*a.x - m10.y*a.y + m11.x*b.x - m11.y*b.y,
                   m10.x*a.y + m10.y*a.x + m11.x*b.y + m11.y*b.x };
        s[i] = n0; s[i + st] = n1;
    }
}

__device__ __forceinline__ void applyCRX(cpx* s, float c, float sn, int ctrl, int tgt)
{
    int cs = 1 << (2 - ctrl), ts = 1 << (2 - tgt);
    for (int i = 0; i < 8; i++) {
        if (!(i & cs) || (i & ts)) continue;
        cpx a = s[i], b = s[i + ts];
        s[i]      = { c*a.x + sn*b.y, c*a.y - sn*b.x };
        s[i + ts] = { c*b.x + sn*a.y, c*b.y - sn*a.x };
    }
}

__global__ void setup_kernel(const float* __restrict__ theta,
                             const float* __restrict__ W1,
                             const float* __restrict__ b1,
                             const float* __restrict__ W2)
{
    __shared__ cpx Vs[4][8];
    int tid = threadIdx.x;

    if (tid < 4) {
        cpx s[8];
        for (int i = 0; i < 8; i++) s[i] = {0.f, 0.f};
        s[tid * 2] = {1.f, 0.f};
        float c, sn;
        sincosf(0.5f * theta[0], &sn, &c);
        apply1q(s, {c,0.f},{0.f,-sn},{0.f,-sn},{c,0.f}, 0);
        sincosf(0.5f * theta[1], &sn, &c);
        apply1q(s, {c,0.f},{-sn,0.f},{sn,0.f},{c,0.f}, 1);
        sincosf(0.5f * theta[2], &sn, &c);
        apply1q(s, {c,-sn},{0.f,0.f},{0.f,0.f},{c,sn}, 2);
        sincosf(0.5f * theta[3], &sn, &c);
        applyCRX(s, c, sn, 0, 1);
        sincosf(0.5f * theta[4], &sn, &c);
        apply1q(s, {c,0.f},{-sn,0.f},{sn,0.f},{c,0.f}, 2);
        sincosf(0.5f * theta[5], &sn, &c);
        apply1q(s, {c,0.f},{0.f,-sn},{0.f,-sn},{c,0.f}, 1);
        sincosf(0.5f * theta[6], &sn, &c);
        applyCRX(s, c, sn, 1, 2);
        sincosf(0.5f * theta[7], &sn, &c);
        apply1q(s, {c,-sn},{0.f,0.f},{0.f,0.f},{c,sn}, 0);
        for (int k = 0; k < 8; k++)
            Vs[tid][k] = (tid >= 2) ? cpx{ s[k].y, -s[k].x } : s[k]; // * (-i)
    }
    __syncwarp();

    int j = tid;
    float M[4][4];
    for (int a = 0; a < 4; a++)
        for (int b = 0; b < 4; b++) {
            float m = 0.f;
            for (int k = 0; k < 8; k++)
                m += W1[k * NHID + j] * (Vs[a][k].x * Vs[b][k].x + Vs[a][k].y * Vs[b][k].y);
            M[a][b] = m;
        }

    const float R[2][2][3] = { { {0.5f, 0.5f, 0.f}, {0.f, 0.f, 0.5f} },
                               { {0.f, 0.f, 0.5f}, {0.5f, -0.5f, 0.f} } };
    float K[3][3] = { {0.f,0.f,0.f},{0.f,0.f,0.f},{0.f,0.f,0.f} };
    for (int a = 0; a < 4; a++)
        for (int b = 0; b < 4; b++) {
            int ia = a >> 1, ja = a & 1, ib = b >> 1, jb = b & 1;
            float Mab = M[a][b];
            for (int m = 0; m < 3; m++)
                for (int n = 0; n < 3; n++)
                    K[m][n] += Mab * R[ia][ib][m] * R[ja][jb][n];
        }
    K[0][0] += b1[j];

    float cf[9];
    for (int t = 0; t < 9; t++) cf[t] = K[t / 3][t % 3];

    for (int t = 0; t < 9; t++) g_const[j * 12 + t] = cf[t];
    g_const[j * 12 + 9]  = W2[j * 2 + 0];
    g_const[j * 12 + 10] = W2[j * 2 + 1];
    g_const[j * 12 + 11] = 0.f;

    // main-GEMM fragments: single k-step, B = f16(K), rows 9-15 zero
    {
        int nt = j >> 3, g = j & 7;
        for (int r = 0; r < 2; r++)
            for (int t = 0; t < 4; t++) {
                int r0 = 2 * t + r * 8;
                float v0 = (r0     < 9) ? cf[r0]     : 0.f;
                float v1 = (r0 + 1 < 9) ? cf[r0 + 1] : 0.f;
                __half2 h2 = __floats2half2_rn(v0, v1);
                g_Bfrag[nt][r][g * 4 + t] = *reinterpret_cast<unsigned int*>(&h2);
            }
    }

    // epilogue B2 fragments (exact W2 via scaled-lo n-columns)
    {
        int g = tid >> 2, t = tid & 3;
        for (int ks = 0; ks < 2; ks++)
            for (int r = 0; r < 2; r++) {
                int k0 = ks * 16 + 2 * t + r * 8;
                float v0 = 0.f, v1 = 0.f;
                if (g < 2) {
                    v0 = W2[k0 * 2 + g];
                    v1 = W2[(k0 + 1) * 2 + g];
                } else if (g < 4) {
                    int c = g - 2;
                    float w0f = W2[k0 * 2 + c];
                    float w1f = W2[(k0 + 1) * 2 + c];
                    v0 = (w0f - __half2float(__float2half_rn(w0f))) * 4096.f;
                    v1 = (w1f - __half2float(__float2half_rn(w1f))) * 4096.f;
                }
                __half2 h2 = __floats2half2_rn(v0, v1);
                g_B2frag[ks][r][tid] = *reinterpret_cast<unsigned int*>(&h2);
            }
    }
}

__device__ __forceinline__ void mma16816(float c[4],
                                         unsigned a0, unsigned a1, unsigned a2, unsigned a3,
                                         unsigned b0, unsigned b1)
{
    asm volatile(
        "mma.sync.aligned.m16n8k16.row.col.f32.f16.f16.f32 "
        "{%0,%1,%2,%3}, {%4,%5,%6,%7}, {%8,%9}, {%0,%1,%2,%3};"
        : "+f"(c[0]), "+f"(c[1]), "+f"(c[2]), "+f"(c[3])
        : "r"(a0), "r"(a1), "r"(a2), "r"(a3), "r"(b0), "r"(b1));
}

__device__ __forceinline__ void ldmatrix_x4(unsigned& a0, unsigned& a1,
                                            unsigned& a2, unsigned& a3,
                                            unsigned saddr)
{
    asm volatile(
        "ldmatrix.sync.aligned.m8n8.x4.shared.b16 {%0,%1,%2,%3}, [%4];"
        : "=r"(a0), "=r"(a1), "=r"(a2), "=r"(a3) : "r"(saddr));
}

// One warp = 64 samples (2 iterations sharing uniform fragments).
// Hidden layer: single-k-step f16 MMA (A=f16(F), B=f16(K)). Output layer:
// MMA on f16(relu(H)) with exact W2 via scaled-lo n-columns.
#define ROWH 24   // sA row stride in halves: 48 B = 3x16 -> uint4-aligned,
                  // and 48 mod 128 walks all bank groups (conflict-free)
__global__ void __launch_bounds__(256, 4)
qmlp_mma(const float* __restrict__ x,
         const float* __restrict__ b2,
         float* __restrict__ out, int B)
{
    __shared__ __align__(16) __half sA[8][32 * ROWH];

    int lane = threadIdx.x & 31;
    int warp = threadIdx.x >> 5;
    long long G = (long long)blockIdx.x * 8 + warp;
    long long wbase = G * 64;
    if (wbase >= B) return;

    int g = lane >> 2, t = lane & 3;
    float bias0 = __ldg(&b2[0]);
    float bias1 = __ldg(&b2[1]);

    // hoisted uniform fragments (shared across both iterations)
    unsigned bf[4][2];
    #pragma unroll
    for (int nt = 0; nt < 4; nt++) {
        bf[nt][0] = __ldg(&g_Bfrag[nt][0][lane]);
        bf[nt][1] = __ldg(&g_Bfrag[nt][1][lane]);
    }
    unsigned b2f[2][2];
    #pragma unroll
    for (int ks = 0; ks < 2; ks++) {
        b2f[ks][0] = __ldg(&g_B2frag[ks][0][lane]);
        b2f[ks][1] = __ldg(&g_B2frag[ks][1][lane]);
    }

    // ldmatrix row addressing: lanes 0-15 -> rows (k 0-7), 16-31 -> (k 8-15)
    int lm_row   = lane & 15;
    int lm_khalf = (lane >> 4) * 8;
    unsigned sbase = (unsigned)__cvta_generic_to_shared(&sA[warp][0]);

    const __half2 hz = __floats2half2_rn(0.f, 0.f);
    const float SCL = 1.f / 4096.f;

    #pragma unroll
    for (int it = 0; it < 2; it++) {
        long long base = wbase + (long long)it * 32;
        if (base >= B) break;

        if (base + 32 <= B) {
            long long S = base + lane;
            float xa = __ldg(&x[S * 3]);
            float xb = __ldg(&x[S * 3 + 1]);      // x[...+2] is a global phase
            float s0n, c0n, s1n, c1n;
            __sincosf(xa, &s0n, &c0n);
            __sincosf(xb, &s1n, &c1n);
            float F[9] = { 1.f, c1n, s1n, c0n, c0n*c1n, c0n*s1n, s0n, s0n*c1n, s0n*s1n };

            // A row (16 halves): cols 0-8 = f16(F), cols 9-15 = 0
            unsigned w[8];
            __half2 h2;
            #define PACK(a, b) (h2 = __floats2half2_rn((a), (b)), *reinterpret_cast<unsigned*>(&h2))
            w[0] = PACK(F[0], F[1]);
            w[1] = PACK(F[2], F[3]);
            w[2] = PACK(F[4], F[5]);
            w[3] = PACK(F[6], F[7]);
            w[4] = PACK(F[8], 0.f);
            w[5] = 0u; w[6] = 0u; w[7] = 0u;
            #undef PACK

            __syncwarp();   // protect sA reuse across iterations
            uint4* rp = reinterpret_cast<uint4*>(&sA[warp][lane * ROWH]);
            rp[0] = make_uint4(w[0], w[1], w[2], w[3]);
            rp[1] = make_uint4(w[4], w[5], w[6], w[7]);
            __syncwarp();

            #pragma unroll
            for (int tile = 0; tile < 2; tile++) {
                float acc[4][4];
                #pragma unroll
                for (int nt = 0; nt < 4; nt++)
                    #pragma unroll
                    for (int c = 0; c < 4; c++) acc[nt][c] = 0.f;

                unsigned lmaddr = sbase +
                    ((unsigned)(tile * 16 + lm_row) * (unsigned)ROWH + (unsigned)lm_khalf) * 2u;
                unsigned a0, a1, a2, a3;
                ldmatrix_x4(a0, a1, a2, a3, lmaddr);
                #pragma unroll
                for (int nt = 0; nt < 4; nt++)
                    mma16816(acc[nt], a0, a1, a2, a3, bf[nt][0], bf[nt][1]);

                // epilogue on the tensor pipe
                unsigned hp[4][2];
                #pragma unroll
                for (int nt = 0; nt < 4; nt++) {
                    __half2 t01 = __floats2half2_rn(acc[nt][0], acc[nt][1]);
                    __half2 t23 = __floats2half2_rn(acc[nt][2], acc[nt][3]);
                    t01 = __hmax2(t01, hz);
                    t23 = __hmax2(t23, hz);
                    hp[nt][0] = *reinterpret_cast<unsigned*>(&t01);
                    hp[nt][1] = *reinterpret_cast<unsigned*>(&t23);
                }
                float o[4] = { 0.f, 0.f, 0.f, 0.f };
                mma16816(o, hp[0][0], hp[0][1], hp[1][0], hp[1][1], b2f[0][0], b2f[0][1]);
                mma16816(o, hp[2][0], hp[2][1], hp[3][0], hp[3][1], b2f[1][0], b2f[1][1]);

                // t=0 lanes: W2_hi (n=0,1); t=1 lanes: scaled W2_lo (n=2,3)
                float cr0 = __shfl_xor_sync(0xffffffffu, o[0], 1);
                float cr1 = __shfl_xor_sync(0xffffffffu, o[1], 1);
                float cr2 = __shfl_xor_sync(0xffffffffu, o[2], 1);
                float cr3 = __shfl_xor_sync(0xffffffffu, o[3], 1);

                if (t == 0) {
                    long long rr = base + tile * 16 + g;
                    float2* ov = reinterpret_cast<float2*>(out);
                    ov[rr]     = make_float2(fmaf(cr0, SCL, o[0]) + bias0,
                                             fmaf(cr1, SCL, o[1]) + bias1);
                    ov[rr + 8] = make_float2(fmaf(cr2, SCL, o[2]) + bias0,
                                             fmaf(cr3, SCL, o[3]) + bias1);
                }
            }
        } else {
            // scalar fp32 tail
            for (long long s = base + lane; s < B; s += 32) {
                float xx0 = x[s * 3], xx1 = x[s * 3 + 1];
                float cc0, ss0, cc1, ss1;
                __sincosf(xx0, &ss0, &cc0);
                __sincosf(xx1, &ss1, &cc1);
                float o0 = bias0, o1 = bias1;
                for (int j = 0; j < NHID; j++) {
                    const float* K = &g_const[j * 12];
                    float t0 = K[0] + K[1]*cc1 + K[2]*ss1;
                    float t1 = K[3] + K[4]*cc1 + K[5]*ss1;
                    float t2 = K[6] + K[7]*cc1 + K[8]*ss1;
                    float h = fmaxf(t0 + cc0*t1 + ss0*t2, 0.f);
                    o0 += h * K[9];
                    o1 += h * K[10];
                }
                out[s * 2]     = o0;
                out[s * 2 + 1] = o1;
            }
            break;
        }
    }
}

extern "C" void kernel_launch(void* const* d_in, const int* in_sizes, int n_in,
                              void* d_out, int out_size)
{
    const float* x     = (const float*)d_in[0];
    const float* theta = (const float*)d_in[1];
    const float* W1    = (const float*)d_in[2];
    const float* b1    = (const float*)d_in[3];
    const float* W2    = (const float*)d_in[4];
    const float* b2    = (const float*)d_in[5];
    int B = in_sizes[0] / 3;

    setup_kernel<<<1, 32>>>(theta, W1, b1, W2);

    long long wgroups = ((long long)B + 63) / 64;
    int nblocks = (int)((wgroups + 7) / 8);
    qmlp_mma<<<nblocks, 256>>>(x, b2, (float*)d_out, B);
}